// round 10
// baseline (speedup 1.0000x reference)
#include <cuda_runtime.h>
#include <cuda_bf16.h>
#include <cstdint>

// ---------------------------------------------------------------------------
// IngredientPositionEncoding: segment-mean pooling + positional encoding.
//
// Kernel 1: per-batch-row separator scan -> int4 meta (flat_start, cnt, s, 0).
// Kernel 2 (fast path): persistent 148 blocks x 8 warps. Each warp streams
//   its rows' token slabs into shared via cp.async.cg (double-buffered, one
//   row ahead), reduces from shared, adds pe, stores. Bytes-in-flight are
//   decoupled from registers/scoreboards -> deeper DRAM pipelining than LDG.
// ---------------------------------------------------------------------------

#define MAX_SEPS_CAP 4096       // >= L
#define MAX_OUT_ROWS 65536      // >= B*max_ingr
#define P_BLOCKS 148            // one block per SM (smem-limited)
#define NWARPS 8                // warps per block
#define CAP_TOK 16              // tokens buffered per row slab

__device__ int4 g_seg_meta[MAX_OUT_ROWS];
__device__ int  g_fallback_max_ingr = 256;

// ---------------------------------------------------------------------------
// cp.async helpers
// ---------------------------------------------------------------------------
__device__ __forceinline__ void cp_async16(unsigned int smem_addr, const void* gptr) {
    asm volatile("cp.async.cg.shared.global [%0], [%1], 16;\n"
                 :: "r"(smem_addr), "l"(gptr));
}
__device__ __forceinline__ void cp_commit() {
    asm volatile("cp.async.commit_group;\n");
}
template <int N>
__device__ __forceinline__ void cp_wait() {
    asm volatile("cp.async.wait_group %0;\n" :: "n"(N));
}

// ---------------------------------------------------------------------------
// Kernel 1: segment boundaries. Grid-stride over batch rows.
// ---------------------------------------------------------------------------
__global__ void __launch_bounds__(256)
seg_bounds_kernel(const int* __restrict__ mask,
                  const int* __restrict__ max_ingr_ptr,
                  int BL, int OUT_ROWS,
                  int4* __restrict__ meta)
{
    const int max_ingr = *max_ingr_ptr;
    const int B = OUT_ROWS / max_ingr;
    const int L = BL / B;

    __shared__ int sh_sep[MAX_SEPS_CAP];
    __shared__ int sh_warp[9];

    const int tid  = threadIdx.x;
    const int lane = tid & 31;
    const int wid  = tid >> 5;
    const int nthr = blockDim.x;

    for (int b = blockIdx.x; b < B; b += gridDim.x) {
        const int* mrow = mask + b * L;
        const int chunk = (L + nthr - 1) / nthr;
        const int beg = tid * chunk;
        const int end = min(beg + chunk, L);

        int c = 0;
        if (((chunk & 3) == 0) && ((L & 3) == 0) && (beg < end)) {
            const int4* m4 = (const int4*)(mrow + beg);
            const int n4 = (end - beg) >> 2;
            for (int i = 0; i < n4; ++i) {
                int4 v = m4[i];
                c += (v.x != 0) + (v.y != 0) + (v.z != 0) + (v.w != 0);
            }
        } else {
            for (int i = beg; i < end; ++i) c += (mrow[i] != 0);
        }

        int inc = c;
        #pragma unroll
        for (int o = 1; o < 32; o <<= 1) {
            int v = __shfl_up_sync(0xffffffffu, inc, o);
            if (lane >= o) inc += v;
        }
        if (lane == 31) sh_warp[wid] = inc;
        __syncthreads();

        if (tid == 0) {
            int acc = 0;
            #pragma unroll
            for (int w = 0; w < 8; ++w) { int t = sh_warp[w]; sh_warp[w] = acc; acc += t; }
            sh_warp[8] = acc;
        }
        __syncthreads();

        const int excl = inc - c + sh_warp[wid];
        const int nsep = sh_warp[8];

        int j = excl;
        for (int i = beg; i < end; ++i) {
            if (mrow[i] != 0) {
                if (j < MAX_SEPS_CAP) sh_sep[j] = i;
                ++j;
            }
        }
        __syncthreads();

        for (int s = tid; s < max_ingr; s += nthr) {
            int start, cnt;
            if (s < nsep) {
                start = (s == 0) ? 0 : (sh_sep[s - 1] + 1);
                cnt   = sh_sep[s] - start;
            } else if (s == nsep) {
                start = (nsep == 0) ? 0 : (sh_sep[nsep - 1] + 1);
                cnt   = L - start;
            } else {
                start = 0;
                cnt   = 0;
            }
            meta[b * max_ingr + s] = make_int4(b * L + start, cnt, s, 0);
        }
        __syncthreads();
    }
}

// ---------------------------------------------------------------------------
// Kernel 2 (fast path): cp.async double-buffered segment-mean.
// Dynamic smem: NWARPS * 2 * CAP_TOK * D4 * 16 bytes.
// ---------------------------------------------------------------------------
__global__ void __launch_bounds__(NWARPS * 32)
seg_mean_ca_kernel(const float4* __restrict__ x4,
                   const float4* __restrict__ pe4,
                   const int4* __restrict__ meta,
                   float4* __restrict__ out4,
                   int D4, int OUT_ROWS)
{
    extern __shared__ float4 sbuf[];   // [NWARPS][2][CAP_TOK * D4]

    const int lane = threadIdx.x & 31;
    const int wid  = threadIdx.x >> 5;
    const int g    = blockIdx.x * NWARPS + wid;      // global warp id
    const int STEP = gridDim.x * NWARPS;

    if (g >= OUT_ROWS) return;

    const int slab = CAP_TOK * D4;                   // float4s per buffer
    float4* buf0 = sbuf + (wid * 2 + 0) * slab;
    float4* buf1 = sbuf + (wid * 2 + 1) * slab;
    const unsigned int sa0 = (unsigned int)__cvta_generic_to_shared(buf0);
    const unsigned int sa1 = (unsigned int)__cvta_generic_to_shared(buf1);

    // issue copy for first row
    int r = g;
    int4 md = meta[r];
    {
        const int use = min(md.y, CAP_TOK);
        const float4* src = x4 + (long long)md.x * D4;
        for (int idx = lane; idx < use * D4; idx += 32)
            cp_async16(sa0 + idx * 16u, src + idx);
    }
    cp_commit();

    int cur = 0;
    while (true) {
        // prefetch next row into the other buffer
        const int rn = r + STEP;
        int4 mdn = make_int4(0, 0, 0, 0);
        if (rn < OUT_ROWS) {
            mdn = meta[rn];
            const int usen = min(mdn.y, CAP_TOK);
            const float4* srcn = x4 + (long long)mdn.x * D4;
            const unsigned int san = cur ? sa0 : sa1;
            for (int idx = lane; idx < usen * D4; idx += 32)
                cp_async16(san + idx * 16u, srcn + idx);
        }
        cp_commit();                 // always one group per iteration
        cp_wait<1>();                // current row's slab is ready

        // reduce current row from shared
        const int start = md.x;
        const int cnt   = md.y;
        const int s     = md.z;
        const int use   = min(cnt, CAP_TOK);
        const float inv = (cnt > 0) ? (1.0f / (float)cnt) : 0.0f;
        const float4* bp = cur ? buf1 : buf0;

        for (int c = lane; c < D4; c += 32) {
            float4 acc = {0.f, 0.f, 0.f, 0.f};
            #pragma unroll 4
            for (int t = 0; t < use; ++t) {
                float4 v = bp[t * D4 + c];
                acc.x += v.x; acc.y += v.y; acc.z += v.z; acc.w += v.w;
            }
            // generic tail for oversized segments (cnt > CAP_TOK)
            for (int t = CAP_TOK; t < cnt; ++t) {
                float4 v = __ldcs(x4 + (long long)(start + t) * D4 + c);
                acc.x += v.x; acc.y += v.y; acc.z += v.z; acc.w += v.w;
            }

            float4 p = pe4[(long long)s * D4 + c];
            float4 o;
            o.x = acc.x * inv + p.x;
            o.y = acc.y * inv + p.y;
            o.z = acc.z * inv + p.z;
            o.w = acc.w * inv + p.w;
            out4[(long long)r * D4 + c] = o;
        }

        if (rn >= OUT_ROWS) break;
        r = rn;
        md = mdn;
        cur ^= 1;
    }
}

// ---------------------------------------------------------------------------
// Kernel 2 (generic fallback, any D): one block per row, thread = channel.
// ---------------------------------------------------------------------------
__global__ void seg_mean_scalar_kernel(const float* __restrict__ x,
                                       const float* __restrict__ pe,
                                       const int4* __restrict__ meta,
                                       float* __restrict__ out,
                                       int D)
{
    const int r = blockIdx.x;
    const int4 md = meta[r];
    const int start = md.x;
    const int cnt   = md.y;
    const int s     = md.z;
    const float inv = (cnt > 0) ? (1.0f / (float)cnt) : 0.0f;

    for (int d = threadIdx.x; d < D; d += blockDim.x) {
        const float* xp = x + (long long)start * D + d;
        float a0 = 0.f, a1 = 0.f, a2 = 0.f, a3 = 0.f;
        int t = 0;
        for (; t + 4 <= cnt; t += 4) {
            a0 += xp[(long long)(t + 0) * D];
            a1 += xp[(long long)(t + 1) * D];
            a2 += xp[(long long)(t + 2) * D];
            a3 += xp[(long long)(t + 3) * D];
        }
        for (; t < cnt; ++t) a0 += xp[(long long)t * D];
        float sum = (a0 + a1) + (a2 + a3);
        out[(long long)r * D + d] = sum * inv + pe[(long long)s * D + d];
    }
}

// ---------------------------------------------------------------------------
// Launch
// ---------------------------------------------------------------------------
extern "C" void kernel_launch(void* const* d_in, const int* in_sizes, int n_in,
                              void* d_out, int out_size)
{
    const float* x    = (const float*)d_in[0];
    const int*   mask = (const int*)d_in[1];
    const float* pe   = (const float*)d_in[2];

    const int* max_ingr_ptr;
    if (n_in >= 4) {
        max_ingr_ptr = (const int*)d_in[3];
    } else {
        int* p = nullptr;
        cudaGetSymbolAddress((void**)&p, g_fallback_max_ingr);
        max_ingr_ptr = p;
    }

    const int x_size    = in_sizes[0];            // B*L*D
    const int mask_size = in_sizes[1];            // B*L
    const int D         = x_size / mask_size;     // 128
    const int OUT_ROWS  = out_size / D;           // B*max_ingr

    int4* meta_p = nullptr;
    cudaGetSymbolAddress((void**)&meta_p, g_seg_meta);

    // Kernel 1: grid-stride over batch rows (B resolved on-device).
    seg_bounds_kernel<<<256, 256>>>(mask, max_ingr_ptr,
                                    mask_size, OUT_ROWS, meta_p);

    const size_t smem_need = (size_t)NWARPS * 2 * CAP_TOK * (D >> 2) * 16;
    if ((D & 3) == 0 && smem_need <= 227 * 1024) {
        const int D4 = D >> 2;
        cudaFuncSetAttribute(seg_mean_ca_kernel,
                             cudaFuncAttributeMaxDynamicSharedMemorySize,
                             (int)smem_need);
        seg_mean_ca_kernel<<<P_BLOCKS, NWARPS * 32, smem_need>>>(
            (const float4*)x, (const float4*)pe, meta_p,
            (float4*)d_out, D4, OUT_ROWS);
    } else {
        seg_mean_scalar_kernel<<<OUT_ROWS, 128>>>(
            x, pe, meta_p, (float*)d_out, D);
    }
}